// round 1
// baseline (speedup 1.0000x reference)
#include <cuda_runtime.h>
#include <math.h>

// Problem constants
#define BSZ   2
#define SEQ   2048
#define EMB   2048
#define NH    32
#define HD    64
#define KVHN  8
#define KVD   512     // KVHN * HD
#define GRP   4       // NH / KVHN
#define MTOT  (BSZ*SEQ)   // 4096

// Scratch (device globals: allocation-free per harness rules)
__device__ float g_q[MTOT * EMB];     // [b*S+s][h*64+d]
__device__ float g_k[MTOT * KVD];     // [b*S+s][kvh*64+d]
__device__ float g_v[MTOT * KVD];
__device__ float g_attn[MTOT * EMB];  // attention output before Wo

// ---------------------------------------------------------------------------
// Generic 64x64 tile fp32 GEMM: C[M,N] = A[M,K] @ B[K,N]
// blockDim = (16,16); each thread computes a 4x4 micro-tile. BK = 16.
// ---------------------------------------------------------------------------
__device__ __forceinline__ void gemm64x64(const float* __restrict__ A,
                                          const float* __restrict__ B,
                                          float* __restrict__ C,
                                          int M, int N, int K)
{
    __shared__ float As[16][65];
    __shared__ float Bs[16][65];
    const int tx = threadIdx.x, ty = threadIdx.y;
    const int tid = ty * 16 + tx;
    const int mBase = blockIdx.y * 64;
    const int nBase = blockIdx.x * 64;

    float acc[4][4] = {};

    for (int k0 = 0; k0 < K; k0 += 16) {
        // load A tile 64x16 (transposed into As[k][m])
        #pragma unroll
        for (int i = 0; i < 4; i++) {
            int idx = tid + i * 256;
            int m = idx >> 4, kk = idx & 15;
            As[kk][m] = A[(size_t)(mBase + m) * K + k0 + kk];
        }
        // load B tile 16x64
        #pragma unroll
        for (int i = 0; i < 4; i++) {
            int idx = tid + i * 256;
            int kk = idx >> 6, n = idx & 63;
            Bs[kk][n] = B[(size_t)(k0 + kk) * N + nBase + n];
        }
        __syncthreads();

        #pragma unroll
        for (int kk = 0; kk < 16; kk++) {
            float a[4], bb[4];
            #pragma unroll
            for (int i = 0; i < 4; i++) a[i] = As[kk][ty * 4 + i];
            #pragma unroll
            for (int j = 0; j < 4; j++) bb[j] = Bs[kk][tx * 4 + j];
            #pragma unroll
            for (int i = 0; i < 4; i++)
                #pragma unroll
                for (int j = 0; j < 4; j++)
                    acc[i][j] = fmaf(a[i], bb[j], acc[i][j]);
        }
        __syncthreads();
    }

    #pragma unroll
    for (int i = 0; i < 4; i++)
        #pragma unroll
        for (int j = 0; j < 4; j++)
            C[(size_t)(mBase + ty * 4 + i) * N + nBase + tx * 4 + j] = acc[i][j];
}

__global__ void k_proj_q(const float* __restrict__ x, const float* __restrict__ Wq) {
    gemm64x64(x, Wq, g_q, MTOT, EMB, EMB);
}
__global__ void k_proj_k(const float* __restrict__ x, const float* __restrict__ Wk) {
    gemm64x64(x, Wk, g_k, MTOT, KVD, EMB);
}
__global__ void k_proj_v(const float* __restrict__ x, const float* __restrict__ Wv) {
    gemm64x64(x, Wv, g_v, MTOT, KVD, EMB);
}
__global__ void k_out_proj(const float* __restrict__ Wo, float* __restrict__ out) {
    gemm64x64(g_attn, Wo, out, MTOT, EMB, EMB);
}

// ---------------------------------------------------------------------------
// Causal GQA flash attention.
// Grid: (SEQ/64, NH, BSZ). Block: (16,16) = 256 threads.
// Each block: 64 queries x head_dim 64, streams causal K/V tiles of 64.
// Dynamic smem: sQ, sK, sV, sS (64 x 65 each) + sM/sL/sScale (64 each).
// ---------------------------------------------------------------------------
#define SMEM_ATTN ((4 * 64 * 65 + 3 * 64) * (int)sizeof(float))

__global__ void attn_kernel()
{
    extern __shared__ float sm[];
    float* sQ = sm;                 // [64][65]
    float* sK = sQ + 64 * 65;
    float* sV = sK + 64 * 65;
    float* sS = sV + 64 * 65;
    float* sM = sS + 64 * 65;       // [64]
    float* sL = sM + 64;
    float* sSc = sL + 64;

    const int qt = blockIdx.x;
    const int h  = blockIdx.y;
    const int b  = blockIdx.z;
    const int kvh = h >> 2;     // h / GRP
    const int tx = threadIdx.x, ty = threadIdx.y;
    const int tid = ty * 16 + tx;
    const float scale = 0.125f; // 1/sqrt(64)

    const int q0 = qt * 64;
    const int r0 = ty * 4, c0 = tx * 4;

    // load Q tile (64 rows x 64 d)
    #pragma unroll
    for (int i = 0; i < 16; i++) {
        int idx = tid + i * 256;
        int r = idx >> 6, d = idx & 63;
        sQ[r * 65 + d] = g_q[(size_t)(b * SEQ + q0 + r) * EMB + h * HD + d];
    }
    if (tid < 64) { sM[tid] = -INFINITY; sL[tid] = 0.f; }
    float o[4][4] = {};
    __syncthreads();

    for (int kt = 0; kt <= qt; kt++) {
        const int k0 = kt * 64;
        // load K and V tiles
        #pragma unroll
        for (int i = 0; i < 16; i++) {
            int idx = tid + i * 256;
            int r = idx >> 6, d = idx & 63;
            size_t base = (size_t)(b * SEQ + k0 + r) * KVD + kvh * HD + d;
            sK[r * 65 + d] = g_k[base];
            sV[r * 65 + d] = g_v[base];
        }
        __syncthreads();

        // scores: S = Q @ K^T (4x4 per thread)
        float s[4][4] = {};
        #pragma unroll 8
        for (int d = 0; d < 64; d++) {
            float a[4], bb[4];
            #pragma unroll
            for (int i = 0; i < 4; i++) a[i]  = sQ[(r0 + i) * 65 + d];
            #pragma unroll
            for (int j = 0; j < 4; j++) bb[j] = sK[(c0 + j) * 65 + d];
            #pragma unroll
            for (int i = 0; i < 4; i++)
                #pragma unroll
                for (int j = 0; j < 4; j++)
                    s[i][j] = fmaf(a[i], bb[j], s[i][j]);
        }
        const bool diag = (kt == qt);
        #pragma unroll
        for (int i = 0; i < 4; i++)
            #pragma unroll
            for (int j = 0; j < 4; j++) {
                float v = s[i][j] * scale;
                if (diag && (k0 + c0 + j > q0 + r0 + i)) v = -INFINITY;
                sS[(r0 + i) * 65 + c0 + j] = v;
            }
        __syncthreads();

        // online softmax per row (threads 0..63 each own one row)
        if (tid < 64) {
            const int r = tid;
            float mOld = sM[r];
            float mx = mOld;
            #pragma unroll 8
            for (int c = 0; c < 64; c++) mx = fmaxf(mx, sS[r * 65 + c]);
            float sc = __expf(mOld - mx);   // 0 on first tile (mOld = -inf)
            float l = sL[r] * sc;
            #pragma unroll 8
            for (int c = 0; c < 64; c++) {
                float p = __expf(sS[r * 65 + c] - mx);
                sS[r * 65 + c] = p;
                l += p;
            }
            sM[r] = mx; sL[r] = l; sSc[r] = sc;
        }
        __syncthreads();

        // rescale accumulator and add P @ V
        float f[4];
        #pragma unroll
        for (int i = 0; i < 4; i++) f[i] = sSc[r0 + i];
        #pragma unroll
        for (int i = 0; i < 4; i++)
            #pragma unroll
            for (int j = 0; j < 4; j++) o[i][j] *= f[i];

        #pragma unroll 8
        for (int c = 0; c < 64; c++) {
            float p[4], vv[4];
            #pragma unroll
            for (int i = 0; i < 4; i++) p[i]  = sS[(r0 + i) * 65 + c];
            #pragma unroll
            for (int j = 0; j < 4; j++) vv[j] = sV[c * 65 + c0 + j];
            #pragma unroll
            for (int i = 0; i < 4; i++)
                #pragma unroll
                for (int j = 0; j < 4; j++)
                    o[i][j] = fmaf(p[i], vv[j], o[i][j]);
        }
        __syncthreads();
    }

    // normalize and write
    #pragma unroll
    for (int i = 0; i < 4; i++) {
        float inv = 1.0f / sL[r0 + i];
        #pragma unroll
        for (int j = 0; j < 4; j++)
            g_attn[(size_t)(b * SEQ + q0 + r0 + i) * EMB + h * HD + c0 + j] = o[i][j] * inv;
    }
}

// ---------------------------------------------------------------------------
extern "C" void kernel_launch(void* const* d_in, const int* in_sizes, int n_in,
                              void* d_out, int out_size)
{
    const float* x  = (const float*)d_in[0];
    const float* Wq = (const float*)d_in[1];
    const float* Wk = (const float*)d_in[2];
    const float* Wv = (const float*)d_in[3];
    const float* Wo = (const float*)d_in[4];
    float* out = (float*)d_out;

    cudaFuncSetAttribute(attn_kernel, cudaFuncAttributeMaxDynamicSharedMemorySize, SMEM_ATTN);

    dim3 blk(16, 16);
    k_proj_q<<<dim3(EMB / 64, MTOT / 64), blk>>>(x, Wq);
    k_proj_k<<<dim3(KVD / 64, MTOT / 64), blk>>>(x, Wk);
    k_proj_v<<<dim3(KVD / 64, MTOT / 64), blk>>>(x, Wv);
    attn_kernel<<<dim3(SEQ / 64, NH, BSZ), blk, SMEM_ATTN>>>();
    k_out_proj<<<dim3(EMB / 64, MTOT / 64), blk>>>(Wo, out);
}

// round 8
// speedup vs baseline: 1.4131x; 1.4131x over previous
#include <cuda_runtime.h>
#include <math.h>
#include <stdint.h>

// Problem constants
#define BSZ   2
#define SEQ   2048
#define EMB   2048
#define NH    32
#define HD    64
#define KVHN  8
#define KVD   512
#define GRP   4
#define MTOT  (BSZ*SEQ)   // 4096

// Scratch — device globals, referenced ONLY inside device code (host-side
// references to __device__ symbols yield the host shadow address: R2-R7 bug).
__device__ __align__(16) float g_q[MTOT * EMB];
__device__ __align__(16) float g_k[MTOT * KVD];
__device__ __align__(16) float g_v[MTOT * KVD];
__device__ __align__(16) float g_attn[MTOT * EMB];

// ---------------------------------------------------------------------------
// fp32 SGEMM body: C[M=4096, N, K] = A @ B. Block tile 128x128, BK=16,
// 256 threads, 8x8 micro-tile, float4 smem fragments, gmem prefetch.
// ---------------------------------------------------------------------------
#define GLD 132   // padded row (floats): 528B rows, 16B-aligned

__device__ __forceinline__
void gemm_body(const float* __restrict__ A, const float* __restrict__ Bg,
               float* __restrict__ C, int N, int K)
{
    __shared__ float As[16][GLD];   // As[k][m] (A transposed)
    __shared__ float Bs[16][GLD];   // Bs[k][n]

    const int tid = threadIdx.x;
    const int tx = tid & 15;
    const int ty = tid >> 4;
    const int m0 = blockIdx.y * 128;
    const int n0 = blockIdx.x * 128;

    int aM[2], aK[2], bR[2], bC[2];
    #pragma unroll
    for (int i = 0; i < 2; i++) {
        int idx4 = tid + i * 256;
        aM[i] = idx4 >> 2;          // 0..127
        aK[i] = (idx4 & 3) * 4;     // 0,4,8,12
        bR[i] = idx4 >> 5;          // 0..15
        bC[i] = (idx4 & 31) * 4;    // 0..124
    }

    float4 pa[2], pb[2];
    #pragma unroll
    for (int i = 0; i < 2; i++) {
        pa[i] = *(const float4*)(A  + (size_t)(m0 + aM[i]) * K + aK[i]);
        pb[i] = *(const float4*)(Bg + (size_t)bR[i] * N + n0 + bC[i]);
    }

    float acc[8][8] = {};

    for (int kc = 0; kc < K; kc += 16) {
        #pragma unroll
        for (int i = 0; i < 2; i++) {
            As[aK[i] + 0][aM[i]] = pa[i].x;
            As[aK[i] + 1][aM[i]] = pa[i].y;
            As[aK[i] + 2][aM[i]] = pa[i].z;
            As[aK[i] + 3][aM[i]] = pa[i].w;
            *(float4*)&Bs[bR[i]][bC[i]] = pb[i];
        }
        __syncthreads();

        if (kc + 16 < K) {
            #pragma unroll
            for (int i = 0; i < 2; i++) {
                pa[i] = *(const float4*)(A  + (size_t)(m0 + aM[i]) * K + kc + 16 + aK[i]);
                pb[i] = *(const float4*)(Bg + (size_t)(kc + 16 + bR[i]) * N + n0 + bC[i]);
            }
        }

        #pragma unroll
        for (int k = 0; k < 16; k++) {
            float a[8], b[8];
            *(float4*)&a[0] = *(const float4*)&As[k][ty * 8];
            *(float4*)&a[4] = *(const float4*)&As[k][ty * 8 + 4];
            *(float4*)&b[0] = *(const float4*)&Bs[k][tx * 4];
            *(float4*)&b[4] = *(const float4*)&Bs[k][64 + tx * 4];
            #pragma unroll
            for (int i = 0; i < 8; i++)
                #pragma unroll
                for (int j = 0; j < 8; j++)
                    acc[i][j] = fmaf(a[i], b[j], acc[i][j]);
        }
        __syncthreads();
    }

    #pragma unroll
    for (int i = 0; i < 8; i++) {
        int row = m0 + ty * 8 + i;
        *(float4*)(C + (size_t)row * N + n0 + tx * 4) =
            make_float4(acc[i][0], acc[i][1], acc[i][2], acc[i][3]);
        *(float4*)(C + (size_t)row * N + n0 + 64 + tx * 4) =
            make_float4(acc[i][4], acc[i][5], acc[i][6], acc[i][7]);
    }
}

// Wrapper kernels: device globals referenced in DEVICE code (correct addresses)
__global__ __launch_bounds__(256, 2)
void k_proj_q(const float* __restrict__ x, const float* __restrict__ Wq) {
    gemm_body(x, Wq, g_q, EMB, EMB);
}
__global__ __launch_bounds__(256, 2)
void k_proj_k(const float* __restrict__ x, const float* __restrict__ Wk) {
    gemm_body(x, Wk, g_k, KVD, EMB);
}
__global__ __launch_bounds__(256, 2)
void k_proj_v(const float* __restrict__ x, const float* __restrict__ Wv) {
    gemm_body(x, Wv, g_v, KVD, EMB);
}
__global__ __launch_bounds__(256, 2)
void k_out_proj(const float* __restrict__ Wo, float* __restrict__ out) {
    gemm_body(g_attn, Wo, out, EMB, EMB);
}

// ---------------------------------------------------------------------------
// Causal GQA flash attention, fp32, vectorized smem layout:
//   sQt[d][r], sKt[d][c] (d-major) -> QK^T inner: 2x LDS.128 + 16 FMA per d
//   sSt[c][r] (scores transposed)  -> PV inner:   2x LDS.128 + 16 FMA per c
// ---------------------------------------------------------------------------
#define AP 68    // padded row (floats): 272B, 16B-aligned
#define SMEM_ATTN ((4 * 64 * AP + 3 * 64) * (int)sizeof(float))

__global__ __launch_bounds__(256)
void attn_kernel()
{
    extern __shared__ float sm[];
    float* sQt = sm;                 // [64][AP]: [d][r]
    float* sKt = sQt + 64 * AP;      // [64][AP]: [d][c]
    float* sV  = sKt + 64 * AP;      // [64][AP]: [c][d]
    float* sSt = sV  + 64 * AP;      // [64][AP]: [c][r]
    float* sM  = sSt + 64 * AP;
    float* sL  = sM + 64;
    float* sSc = sL + 64;

    const int qt = blockIdx.x;
    const int h  = blockIdx.y;
    const int b  = blockIdx.z;
    const int kvh = h >> 2;
    const int tx = threadIdx.x, ty = threadIdx.y;
    const int tid = ty * 16 + tx;
    const float scale = 0.125f;
    const int q0 = qt * 64;
    const int r0 = ty * 4, c0 = tx * 4;

    #pragma unroll
    for (int i = 0; i < 16; i++) {
        int idx = tid + i * 256;
        int r = idx >> 6, d = idx & 63;
        sQt[d * AP + r] = g_q[(size_t)(b * SEQ + q0 + r) * EMB + h * HD + d];
    }
    if (tid < 64) { sM[tid] = -INFINITY; sL[tid] = 0.f; }
    float o[4][4] = {};
    __syncthreads();

    for (int kt = 0; kt <= qt; kt++) {
        const int k0 = kt * 64;
        #pragma unroll
        for (int i = 0; i < 16; i++) {
            int idx = tid + i * 256;
            int r = idx >> 6, d = idx & 63;
            size_t base = (size_t)(b * SEQ + k0 + r) * KVD + kvh * HD + d;
            sKt[d * AP + r] = g_k[base];
            sV[r * AP + d]  = g_v[base];
        }
        __syncthreads();

        // scores S[r][c] = sum_d Q[r][d] K[c][d]
        float s[4][4] = {};
        #pragma unroll 8
        for (int d = 0; d < 64; d++) {
            float4 q  = *(const float4*)&sQt[d * AP + r0];
            float4 kk = *(const float4*)&sKt[d * AP + c0];
            float qa[4] = {q.x, q.y, q.z, q.w};
            float ka[4] = {kk.x, kk.y, kk.z, kk.w};
            #pragma unroll
            for (int i = 0; i < 4; i++)
                #pragma unroll
                for (int j = 0; j < 4; j++)
                    s[i][j] = fmaf(qa[i], ka[j], s[i][j]);
        }
        const bool diag = (kt == qt);
        #pragma unroll
        for (int j = 0; j < 4; j++) {
            float w[4];
            #pragma unroll
            for (int i = 0; i < 4; i++) {
                float v = s[i][j] * scale;
                if (diag && (k0 + c0 + j > q0 + r0 + i)) v = -INFINITY;
                w[i] = v;
            }
            *(float4*)&sSt[(c0 + j) * AP + r0] = make_float4(w[0], w[1], w[2], w[3]);
        }
        __syncthreads();

        // online softmax: thread r owns query row r (column r of sSt)
        if (tid < 64) {
            const int r = tid;
            float mOld = sM[r];
            float mx = mOld;
            #pragma unroll 8
            for (int c = 0; c < 64; c++) mx = fmaxf(mx, sSt[c * AP + r]);
            float sc = __expf(mOld - mx);
            float l = sL[r] * sc;
            #pragma unroll 8
            for (int c = 0; c < 64; c++) {
                float p = __expf(sSt[c * AP + r] - mx);
                sSt[c * AP + r] = p;
                l += p;
            }
            sM[r] = mx; sL[r] = l; sSc[r] = sc;
        }
        __syncthreads();

        // rescale accumulator, add P @ V
        #pragma unroll
        for (int i = 0; i < 4; i++) {
            float f = sSc[r0 + i];
            #pragma unroll
            for (int j = 0; j < 4; j++) o[i][j] *= f;
        }
        #pragma unroll 8
        for (int c = 0; c < 64; c++) {
            float4 p = *(const float4*)&sSt[c * AP + r0];
            float4 v = *(const float4*)&sV[c * AP + c0];
            float pa[4] = {p.x, p.y, p.z, p.w};
            float va[4] = {v.x, v.y, v.z, v.w};
            #pragma unroll
            for (int i = 0; i < 4; i++)
                #pragma unroll
                for (int j = 0; j < 4; j++)
                    o[i][j] = fmaf(pa[i], va[j], o[i][j]);
        }
        __syncthreads();
    }

    #pragma unroll
    for (int i = 0; i < 4; i++) {
        float inv = 1.0f / sL[r0 + i];
        *(float4*)(g_attn + (size_t)(b * SEQ + q0 + r0 + i) * EMB + h * HD + c0) =
            make_float4(o[i][0] * inv, o[i][1] * inv, o[i][2] * inv, o[i][3] * inv);
    }
}

// ---------------------------------------------------------------------------
extern "C" void kernel_launch(void* const* d_in, const int* in_sizes, int n_in,
                              void* d_out, int out_size)
{
    const float* x  = (const float*)d_in[0];
    const float* Wq = (const float*)d_in[1];
    const float* Wk = (const float*)d_in[2];
    const float* Wv = (const float*)d_in[3];
    const float* Wo = (const float*)d_in[4];
    float* out = (float*)d_out;

    cudaFuncSetAttribute(attn_kernel, cudaFuncAttributeMaxDynamicSharedMemorySize, SMEM_ATTN);

    k_proj_q<<<dim3(EMB / 128, MTOT / 128), 256>>>(x, Wq);
    k_proj_k<<<dim3(KVD / 128, MTOT / 128), 256>>>(x, Wk);
    k_proj_v<<<dim3(KVD / 128, MTOT / 128), 256>>>(x, Wv);

    dim3 blk(16, 16);
    attn_kernel<<<dim3(SEQ / 64, NH, BSZ), blk, SMEM_ATTN>>>();

    k_out_proj<<<dim3(EMB / 128, MTOT / 128), 256>>>(Wo, out);
}

// round 9
// speedup vs baseline: 1.9204x; 1.3590x over previous
#include <cuda_runtime.h>
#include <math.h>
#include <stdint.h>

// Problem constants
#define BSZ   2
#define SEQ   2048
#define EMB   2048
#define NH    32
#define HD    64
#define KVHN  8
#define KVD   512
#define GRP   4
#define MTOT  (BSZ*SEQ)   // 4096

// Scratch — device globals, referenced ONLY inside device code.
__device__ __align__(16) float g_q[MTOT * EMB];
__device__ __align__(16) float g_k[MTOT * KVD];
__device__ __align__(16) float g_v[MTOT * KVD];
__device__ __align__(16) float g_attn[MTOT * EMB];

// ---------------------------------------------------------------------------
// PTX helpers
// ---------------------------------------------------------------------------
__device__ __forceinline__ uint32_t smem_u32(const void* p) {
    return (uint32_t)__cvta_generic_to_shared(p);
}
__device__ __forceinline__ void cp_async16(uint32_t dst, const void* src) {
    asm volatile("cp.async.cg.shared.global [%0], [%1], 16;" :: "r"(dst), "l"(src));
}
__device__ __forceinline__ void cp_commit() {
    asm volatile("cp.async.commit_group;");
}
template<int N>
__device__ __forceinline__ void cp_wait() {
    asm volatile("cp.async.wait_group %0;" :: "n"(N));
}
// pack two fp32 into bf16x2: low half = v0, high half = v1
__device__ __forceinline__ uint32_t pack_bf16x2(float v0, float v1) {
    uint32_t r;
    asm("cvt.rn.bf16x2.f32 %0, %1, %2;" : "=r"(r) : "f"(v1), "f"(v0));
    return r;
}
// split (v0,v1) into bf16 hi pair + bf16 lo (residual) pair
__device__ __forceinline__ void split_pair(float v0, float v1, uint32_t& hi, uint32_t& lo) {
    hi = pack_bf16x2(v0, v1);
    float h0 = __uint_as_float(hi << 16);
    float h1 = __uint_as_float(hi & 0xffff0000u);
    lo = pack_bf16x2(v0 - h0, v1 - h1);
}
__device__ __forceinline__ void mma_bf16(float* c, const uint32_t* a, const uint32_t* b) {
    asm volatile(
        "mma.sync.aligned.m16n8k16.row.col.f32.bf16.bf16.f32 "
        "{%0,%1,%2,%3},{%4,%5,%6,%7},{%8,%9},{%0,%1,%2,%3};"
        : "+f"(c[0]), "+f"(c[1]), "+f"(c[2]), "+f"(c[3])
        : "r"(a[0]), "r"(a[1]), "r"(a[2]), "r"(a[3]), "r"(b[0]), "r"(b[1]));
}

// ---------------------------------------------------------------------------
// Split-bf16 tensor-core GEMM body: C[M,N] = A[M,K] @ B[K,N], fp32 storage.
// Block tile 128x128, K-chunk 32, 256 threads (8 warps 2x4), warp tile 64x32.
// Double-buffered cp.async. 3-term hi/lo product (~3e-5 rel err).
// ---------------------------------------------------------------------------
#define BM 128
#define BN 128
#define BK 32
#define LDA 36
#define LDB 136
#define SMEM_GEMM ((2 * BM * LDA + 2 * BK * LDB) * (int)sizeof(float))  // 71680 B

__device__ __forceinline__
void gemm_body(const float* __restrict__ A, const float* __restrict__ Bg,
               float* __restrict__ C, int N, int K)
{
    extern __shared__ float smem[];
    float* As = smem;                       // [2][BM*LDA]
    float* Bs = smem + 2 * BM * LDA;        // [2][BK*LDB]

    const int tid  = threadIdx.x;
    const int lane = tid & 31;
    const int wid  = tid >> 5;
    const int wm   = wid & 1;               // 0..1
    const int wn   = wid >> 1;              // 0..3
    const int m0   = blockIdx.y * BM;
    const int n0   = blockIdx.x * BN;

    const int lg  = lane >> 2;              // groupID 0..7
    const int lt  = lane & 3;               // thread-in-group 0..3

    float acc[4][4][4] = {};                // [mi][ni][reg]

    auto loadA = [&](int stage, int kc) {
        const float* src = A + (size_t)m0 * K + kc * BK;
        float* dst = As + stage * BM * LDA;
        #pragma unroll
        for (int i = 0; i < 4; i++) {
            int c = tid + i * 256;
            int r = c >> 3, col = (c & 7) * 4;
            cp_async16(smem_u32(dst + r * LDA + col), src + (size_t)r * K + col);
        }
    };
    auto loadB = [&](int stage, int kc) {
        const float* src = Bg + (size_t)(kc * BK) * N + n0;
        float* dst = Bs + stage * BK * LDB;
        #pragma unroll
        for (int i = 0; i < 4; i++) {
            int c = tid + i * 256;
            int r = c >> 5, col = (c & 31) * 4;
            cp_async16(smem_u32(dst + r * LDB + col), src + (size_t)r * N + col);
        }
    };

    const int nk = K / BK;
    loadA(0, 0); loadB(0, 0); cp_commit();

    for (int kc = 0; kc < nk; kc++) {
        const int cur = kc & 1;
        if (kc + 1 < nk) {
            loadA(cur ^ 1, kc + 1); loadB(cur ^ 1, kc + 1); cp_commit();
            cp_wait<1>();
        } else {
            cp_wait<0>();
        }
        __syncthreads();

        const float* a = As + cur * BM * LDA + (wm * 64) * LDA;
        const float* b = Bs + cur * BK * LDB + wn * 32;

        #pragma unroll
        for (int ks = 0; ks < 2; ks++) {
            const int k = ks * 16;
            uint32_t ah[4][4], al[4][4];
            #pragma unroll
            for (int mi = 0; mi < 4; mi++) {
                const float* ap = a + (mi * 16 + lg) * LDA + k;
                float2 v00 = *(const float2*)(ap + 2 * lt);
                float2 v10 = *(const float2*)(ap + 8 * LDA + 2 * lt);
                float2 v01 = *(const float2*)(ap + 2 * lt + 8);
                float2 v11 = *(const float2*)(ap + 8 * LDA + 2 * lt + 8);
                split_pair(v00.x, v00.y, ah[mi][0], al[mi][0]);
                split_pair(v10.x, v10.y, ah[mi][1], al[mi][1]);
                split_pair(v01.x, v01.y, ah[mi][2], al[mi][2]);
                split_pair(v11.x, v11.y, ah[mi][3], al[mi][3]);
            }
            uint32_t bh[4][2], bl[4][2];
            #pragma unroll
            for (int ni = 0; ni < 4; ni++) {
                const float* bp = b + k * LDB + ni * 8 + lg;
                float r0 = bp[(2 * lt) * LDB];
                float r1 = bp[(2 * lt + 1) * LDB];
                float r2 = bp[(2 * lt + 8) * LDB];
                float r3 = bp[(2 * lt + 9) * LDB];
                split_pair(r0, r1, bh[ni][0], bl[ni][0]);
                split_pair(r2, r3, bh[ni][1], bl[ni][1]);
            }
            #pragma unroll
            for (int mi = 0; mi < 4; mi++)
                #pragma unroll
                for (int ni = 0; ni < 4; ni++) {
                    mma_bf16(acc[mi][ni], ah[mi], bh[ni]);
                    mma_bf16(acc[mi][ni], ah[mi], bl[ni]);
                    mma_bf16(acc[mi][ni], al[mi], bh[ni]);
                }
        }
        __syncthreads();
    }

    #pragma unroll
    for (int mi = 0; mi < 4; mi++) {
        #pragma unroll
        for (int ni = 0; ni < 4; ni++) {
            int row = m0 + wm * 64 + mi * 16 + lg;
            int col = n0 + wn * 32 + ni * 8 + 2 * lt;
            float2 v0 = make_float2(acc[mi][ni][0], acc[mi][ni][1]);
            float2 v1 = make_float2(acc[mi][ni][2], acc[mi][ni][3]);
            *(float2*)(C + (size_t)row * N + col)       = v0;
            *(float2*)(C + (size_t)(row + 8) * N + col) = v1;
        }
    }
}

// Wrapper kernels: device globals referenced in DEVICE code only.
__global__ __launch_bounds__(256)
void k_proj_q(const float* __restrict__ x, const float* __restrict__ Wq) {
    gemm_body(x, Wq, g_q, EMB, EMB);
}
__global__ __launch_bounds__(256)
void k_proj_k(const float* __restrict__ x, const float* __restrict__ Wk) {
    gemm_body(x, Wk, g_k, KVD, EMB);
}
__global__ __launch_bounds__(256)
void k_proj_v(const float* __restrict__ x, const float* __restrict__ Wv) {
    gemm_body(x, Wv, g_v, KVD, EMB);
}
__global__ __launch_bounds__(256)
void k_out_proj(const float* __restrict__ Wo, float* __restrict__ out) {
    gemm_body(g_attn, Wo, out, EMB, EMB);
}

// ---------------------------------------------------------------------------
// Causal GQA flash attention (R8 proven kernel, unchanged)
// ---------------------------------------------------------------------------
#define AP 68
#define SMEM_ATTN ((4 * 64 * AP + 3 * 64) * (int)sizeof(float))

__global__ __launch_bounds__(256)
void attn_kernel()
{
    extern __shared__ float sm[];
    float* sQt = sm;                 // [64][AP]: [d][r]
    float* sKt = sQt + 64 * AP;      // [64][AP]: [d][c]
    float* sV  = sKt + 64 * AP;      // [64][AP]: [c][d]
    float* sSt = sV  + 64 * AP;      // [64][AP]: [c][r]
    float* sM  = sSt + 64 * AP;
    float* sL  = sM + 64;
    float* sSc = sL + 64;

    const int qt = blockIdx.x;
    const int h  = blockIdx.y;
    const int b  = blockIdx.z;
    const int kvh = h >> 2;
    const int tx = threadIdx.x, ty = threadIdx.y;
    const int tid = ty * 16 + tx;
    const float scale = 0.125f;
    const int q0 = qt * 64;
    const int r0 = ty * 4, c0 = tx * 4;

    #pragma unroll
    for (int i = 0; i < 16; i++) {
        int idx = tid + i * 256;
        int r = idx >> 6, d = idx & 63;
        sQt[d * AP + r] = g_q[(size_t)(b * SEQ + q0 + r) * EMB + h * HD + d];
    }
    if (tid < 64) { sM[tid] = -INFINITY; sL[tid] = 0.f; }
    float o[4][4] = {};
    __syncthreads();

    for (int kt = 0; kt <= qt; kt++) {
        const int k0 = kt * 64;
        #pragma unroll
        for (int i = 0; i < 16; i++) {
            int idx = tid + i * 256;
            int r = idx >> 6, d = idx & 63;
            size_t base = (size_t)(b * SEQ + k0 + r) * KVD + kvh * HD + d;
            sKt[d * AP + r] = g_k[base];
            sV[r * AP + d]  = g_v[base];
        }
        __syncthreads();

        float s[4][4] = {};
        #pragma unroll 8
        for (int d = 0; d < 64; d++) {
            float4 q  = *(const float4*)&sQt[d * AP + r0];
            float4 kk = *(const float4*)&sKt[d * AP + c0];
            float qa[4] = {q.x, q.y, q.z, q.w};
            float ka[4] = {kk.x, kk.y, kk.z, kk.w};
            #pragma unroll
            for (int i = 0; i < 4; i++)
                #pragma unroll
                for (int j = 0; j < 4; j++)
                    s[i][j] = fmaf(qa[i], ka[j], s[i][j]);
        }
        const bool diag = (kt == qt);
        #pragma unroll
        for (int j = 0; j < 4; j++) {
            float w[4];
            #pragma unroll
            for (int i = 0; i < 4; i++) {
                float v = s[i][j] * scale;
                if (diag && (k0 + c0 + j > q0 + r0 + i)) v = -INFINITY;
                w[i] = v;
            }
            *(float4*)&sSt[(c0 + j) * AP + r0] = make_float4(w[0], w[1], w[2], w[3]);
        }
        __syncthreads();

        if (tid < 64) {
            const int r = tid;
            float mOld = sM[r];
            float mx = mOld;
            #pragma unroll 8
            for (int c = 0; c < 64; c++) mx = fmaxf(mx, sSt[c * AP + r]);
            float sc = __expf(mOld - mx);
            float l = sL[r] * sc;
            #pragma unroll 8
            for (int c = 0; c < 64; c++) {
                float p = __expf(sSt[c * AP + r] - mx);
                sSt[c * AP + r] = p;
                l += p;
            }
            sM[r] = mx; sL[r] = l; sSc[r] = sc;
        }
        __syncthreads();

        #pragma unroll
        for (int i = 0; i < 4; i++) {
            float f = sSc[r0 + i];
            #pragma unroll
            for (int j = 0; j < 4; j++) o[i][j] *= f;
        }
        #pragma unroll 8
        for (int c = 0; c < 64; c++) {
            float4 p = *(const float4*)&sSt[c * AP + r0];
            float4 v = *(const float4*)&sV[c * AP + c0];
            float pa[4] = {p.x, p.y, p.z, p.w};
            float va[4] = {v.x, v.y, v.z, v.w};
            #pragma unroll
            for (int i = 0; i < 4; i++)
                #pragma unroll
                for (int j = 0; j < 4; j++)
                    o[i][j] = fmaf(pa[i], va[j], o[i][j]);
        }
        __syncthreads();
    }

    #pragma unroll
    for (int i = 0; i < 4; i++) {
        float inv = 1.0f / sL[r0 + i];
        *(float4*)(g_attn + (size_t)(b * SEQ + q0 + r0 + i) * EMB + h * HD + c0) =
            make_float4(o[i][0] * inv, o[i][1] * inv, o[i][2] * inv, o[i][3] * inv);
    }
}

// ---------------------------------------------------------------------------
extern "C" void kernel_launch(void* const* d_in, const int* in_sizes, int n_in,
                              void* d_out, int out_size)
{
    const float* x  = (const float*)d_in[0];
    const float* Wq = (const float*)d_in[1];
    const float* Wk = (const float*)d_in[2];
    const float* Wv = (const float*)d_in[3];
    const float* Wo = (const float*)d_in[4];
    float* out = (float*)d_out;

    cudaFuncSetAttribute(k_proj_q,  cudaFuncAttributeMaxDynamicSharedMemorySize, SMEM_GEMM);
    cudaFuncSetAttribute(k_proj_k,  cudaFuncAttributeMaxDynamicSharedMemorySize, SMEM_GEMM);
    cudaFuncSetAttribute(k_proj_v,  cudaFuncAttributeMaxDynamicSharedMemorySize, SMEM_GEMM);
    cudaFuncSetAttribute(k_out_proj, cudaFuncAttributeMaxDynamicSharedMemorySize, SMEM_GEMM);
    cudaFuncSetAttribute(attn_kernel, cudaFuncAttributeMaxDynamicSharedMemorySize, SMEM_ATTN);

    k_proj_q<<<dim3(EMB / BN, MTOT / BM), 256, SMEM_GEMM>>>(x, Wq);
    k_proj_k<<<dim3(KVD / BN, MTOT / BM), 256, SMEM_GEMM>>>(x, Wk);
    k_proj_v<<<dim3(KVD / BN, MTOT / BM), 256, SMEM_GEMM>>>(x, Wv);

    dim3 blk(16, 16);
    attn_kernel<<<dim3(SEQ / 64, NH, BSZ), blk, SMEM_ATTN>>>();

    k_out_proj<<<dim3(EMB / BN, MTOT / BM), 256, SMEM_GEMM>>>(Wo, out);
}

// round 10
// speedup vs baseline: 2.8275x; 1.4724x over previous
#include <cuda_runtime.h>
#include <math.h>
#include <stdint.h>

// Problem constants
#define BSZ   2
#define SEQ   2048
#define EMB   2048
#define NH    32
#define HD    64
#define KVHN  8
#define KVD   512
#define GRP   4
#define MTOT  (BSZ*SEQ)   // 4096

// Scratch — device globals, referenced ONLY inside device code.
__device__ __align__(16) float g_q[MTOT * EMB];
__device__ __align__(16) float g_k[MTOT * KVD];
__device__ __align__(16) float g_v[MTOT * KVD];
__device__ __align__(16) float g_attn[MTOT * EMB];

// ---------------------------------------------------------------------------
// PTX helpers
// ---------------------------------------------------------------------------
__device__ __forceinline__ uint32_t smem_u32(const void* p) {
    return (uint32_t)__cvta_generic_to_shared(p);
}
__device__ __forceinline__ void cp_async16(uint32_t dst, const void* src) {
    asm volatile("cp.async.cg.shared.global [%0], [%1], 16;" :: "r"(dst), "l"(src));
}
__device__ __forceinline__ void cp_commit() {
    asm volatile("cp.async.commit_group;");
}
template<int N>
__device__ __forceinline__ void cp_wait() {
    asm volatile("cp.async.wait_group %0;" :: "n"(N));
}
__device__ __forceinline__ uint32_t pack_bf16x2(float v0, float v1) {
    uint32_t r;
    asm("cvt.rn.bf16x2.f32 %0, %1, %2;" : "=r"(r) : "f"(v1), "f"(v0));
    return r;
}
__device__ __forceinline__ void split_pair(float v0, float v1, uint32_t& hi, uint32_t& lo) {
    hi = pack_bf16x2(v0, v1);
    float h0 = __uint_as_float(hi << 16);
    float h1 = __uint_as_float(hi & 0xffff0000u);
    lo = pack_bf16x2(v0 - h0, v1 - h1);
}
__device__ __forceinline__ void mma_bf16(float* c, const uint32_t* a, const uint32_t* b) {
    asm volatile(
        "mma.sync.aligned.m16n8k16.row.col.f32.bf16.bf16.f32 "
        "{%0,%1,%2,%3},{%4,%5,%6,%7},{%8,%9},{%0,%1,%2,%3};"
        : "+f"(c[0]), "+f"(c[1]), "+f"(c[2]), "+f"(c[3])
        : "r"(a[0]), "r"(a[1]), "r"(a[2]), "r"(a[3]), "r"(b[0]), "r"(b[1]));
}

// ---------------------------------------------------------------------------
// Split-bf16 tensor-core GEMM body (R9-proven): C[M,N] = A[M,K] @ B[K,N].
// Block tile 128x128, BK=32, 256 threads (8 warps 2x4), double-buffered cp.async.
// ---------------------------------------------------------------------------
#define BM 128
#define BN 128
#define BK 32
#define LDA 36
#define LDB 136
#define SMEM_GEMM ((2 * BM * LDA + 2 * BK * LDB) * (int)sizeof(float))  // 71680 B

__device__ __forceinline__
void gemm_body(const float* __restrict__ A, const float* __restrict__ Bg,
               float* __restrict__ C, int N, int K, int bx)
{
    extern __shared__ float smem[];
    float* As = smem;
    float* Bs = smem + 2 * BM * LDA;

    const int tid  = threadIdx.x;
    const int lane = tid & 31;
    const int wid  = tid >> 5;
    const int wm   = wid & 1;
    const int wn   = wid >> 1;
    const int m0   = blockIdx.y * BM;
    const int n0   = bx * BN;

    const int lg  = lane >> 2;
    const int lt  = lane & 3;

    float acc[4][4][4] = {};

    auto loadA = [&](int stage, int kc) {
        const float* src = A + (size_t)m0 * K + kc * BK;
        float* dst = As + stage * BM * LDA;
        #pragma unroll
        for (int i = 0; i < 4; i++) {
            int c = tid + i * 256;
            int r = c >> 3, col = (c & 7) * 4;
            cp_async16(smem_u32(dst + r * LDA + col), src + (size_t)r * K + col);
        }
    };
    auto loadB = [&](int stage, int kc) {
        const float* src = Bg + (size_t)(kc * BK) * N + n0;
        float* dst = Bs + stage * BK * LDB;
        #pragma unroll
        for (int i = 0; i < 4; i++) {
            int c = tid + i * 256;
            int r = c >> 5, col = (c & 31) * 4;
            cp_async16(smem_u32(dst + r * LDB + col), src + (size_t)r * N + col);
        }
    };

    const int nk = K / BK;
    loadA(0, 0); loadB(0, 0); cp_commit();

    for (int kc = 0; kc < nk; kc++) {
        const int cur = kc & 1;
        if (kc + 1 < nk) {
            loadA(cur ^ 1, kc + 1); loadB(cur ^ 1, kc + 1); cp_commit();
            cp_wait<1>();
        } else {
            cp_wait<0>();
        }
        __syncthreads();

        const float* a = As + cur * BM * LDA + (wm * 64) * LDA;
        const float* b = Bs + cur * BK * LDB + wn * 32;

        #pragma unroll
        for (int ks = 0; ks < 2; ks++) {
            const int k = ks * 16;
            uint32_t ah[4][4], al[4][4];
            #pragma unroll
            for (int mi = 0; mi < 4; mi++) {
                const float* ap = a + (mi * 16 + lg) * LDA + k;
                float2 v00 = *(const float2*)(ap + 2 * lt);
                float2 v10 = *(const float2*)(ap + 8 * LDA + 2 * lt);
                float2 v01 = *(const float2*)(ap + 2 * lt + 8);
                float2 v11 = *(const float2*)(ap + 8 * LDA + 2 * lt + 8);
                split_pair(v00.x, v00.y, ah[mi][0], al[mi][0]);
                split_pair(v10.x, v10.y, ah[mi][1], al[mi][1]);
                split_pair(v01.x, v01.y, ah[mi][2], al[mi][2]);
                split_pair(v11.x, v11.y, ah[mi][3], al[mi][3]);
            }
            uint32_t bh[4][2], bl[4][2];
            #pragma unroll
            for (int ni = 0; ni < 4; ni++) {
                const float* bp = b + k * LDB + ni * 8 + lg;
                float r0 = bp[(2 * lt) * LDB];
                float r1 = bp[(2 * lt + 1) * LDB];
                float r2 = bp[(2 * lt + 8) * LDB];
                float r3 = bp[(2 * lt + 9) * LDB];
                split_pair(r0, r1, bh[ni][0], bl[ni][0]);
                split_pair(r2, r3, bh[ni][1], bl[ni][1]);
            }
            #pragma unroll
            for (int mi = 0; mi < 4; mi++)
                #pragma unroll
                for (int ni = 0; ni < 4; ni++) {
                    mma_bf16(acc[mi][ni], ah[mi], bh[ni]);
                    mma_bf16(acc[mi][ni], ah[mi], bl[ni]);
                    mma_bf16(acc[mi][ni], al[mi], bh[ni]);
                }
        }
        __syncthreads();
    }

    #pragma unroll
    for (int mi = 0; mi < 4; mi++) {
        #pragma unroll
        for (int ni = 0; ni < 4; ni++) {
            int row = m0 + wm * 64 + mi * 16 + lg;
            int col = n0 + wn * 32 + ni * 8 + 2 * lt;
            float2 v0 = make_float2(acc[mi][ni][0], acc[mi][ni][1]);
            float2 v1 = make_float2(acc[mi][ni][2], acc[mi][ni][3]);
            *(float2*)(C + (size_t)row * N + col)       = v0;
            *(float2*)(C + (size_t)(row + 8) * N + col) = v1;
        }
    }
}

// Fused Q/K/V projection: grid.x 0..15 -> Q, 16..19 -> K, 20..23 -> V
__global__ __launch_bounds__(256)
void k_proj_qkv(const float* __restrict__ x, const float* __restrict__ Wq,
                const float* __restrict__ Wk, const float* __restrict__ Wv) {
    int bx = blockIdx.x;
    if (bx < 16)      gemm_body(x, Wq, g_q, EMB, EMB, bx);
    else if (bx < 20) gemm_body(x, Wk, g_k, KVD, EMB, bx - 16);
    else              gemm_body(x, Wv, g_v, KVD, EMB, bx - 20);
}
__global__ __launch_bounds__(256)
void k_out_proj(const float* __restrict__ Wo, float* __restrict__ out) {
    gemm_body(g_attn, Wo, out, EMB, EMB, blockIdx.x);
}

// ---------------------------------------------------------------------------
// Tensor-core causal GQA flash attention (FA2-style, split-bf16 mma).
// Grid (SEQ/64, NH, BSZ), 128 threads = 4 warps x 16 q-rows.
// Q frags in regs (scaled by 0.125*log2e), scores+softmax in registers,
// P reused as A-fragment (acc layout == A-frag layout), 3-term split PV.
// ---------------------------------------------------------------------------
#define APK 72   // sK pad: conflict-free for B-frag float2 loads
#define APV 68   // sV pad: conflict-free for B-frag scalar loads

__global__ __launch_bounds__(128)
void attn_tc()
{
    __shared__ float sK[64][APK];
    __shared__ float sV[64][APV];

    const int qt = blockIdx.x, h = blockIdx.y, b = blockIdx.z;
    const int kvh = h >> 2;
    const int tid = threadIdx.x;
    const int w = tid >> 5, lane = tid & 31;
    const int lg = lane >> 2, lt = lane & 3;
    const int q0 = qt * 64;
    const int qrow = q0 + w * 16;
    const float qscale = 0.125f * 1.44269504f;   // fold softmax scale + log2(e)

    // Q fragments (hi/lo), loaded once
    uint32_t qh[4][4], ql[4][4];
    {
        const float* qp = g_q + (size_t)(b * SEQ + qrow) * EMB + h * HD;
        #pragma unroll
        for (int ks = 0; ks < 4; ks++) {
            int d0 = ks * 16 + 2 * lt;
            float2 v00 = *(const float2*)(qp + (size_t)lg * EMB + d0);
            float2 v10 = *(const float2*)(qp + (size_t)(lg + 8) * EMB + d0);
            float2 v01 = *(const float2*)(qp + (size_t)lg * EMB + d0 + 8);
            float2 v11 = *(const float2*)(qp + (size_t)(lg + 8) * EMB + d0 + 8);
            split_pair(v00.x * qscale, v00.y * qscale, qh[ks][0], ql[ks][0]);
            split_pair(v10.x * qscale, v10.y * qscale, qh[ks][1], ql[ks][1]);
            split_pair(v01.x * qscale, v01.y * qscale, qh[ks][2], ql[ks][2]);
            split_pair(v11.x * qscale, v11.y * qscale, qh[ks][3], ql[ks][3]);
        }
    }

    float m_lo = -1e30f, m_hi = -1e30f;
    float l_lo = 0.f, l_hi = 0.f;
    float o[8][4] = {};

    for (int kt = 0; kt <= qt; kt++) {
        const int k0 = kt * 64;
        __syncthreads();
        // fill K, V tiles (64x64 each)
        #pragma unroll
        for (int i = 0; i < 8; i++) {
            int idx = tid + i * 128;
            int r = idx >> 4, c4 = (idx & 15) * 4;
            size_t base = (size_t)(b * SEQ + k0 + r) * KVD + kvh * HD + c4;
            *(float4*)&sK[r][c4] = *(const float4*)(g_k + base);
            *(float4*)&sV[r][c4] = *(const float4*)(g_v + base);
        }
        __syncthreads();

        // ---- S = Q @ K^T (split-bf16 mma; acc = log2-scaled scores) ----
        float s[8][4] = {};
        #pragma unroll
        for (int ks = 0; ks < 4; ks++) {
            #pragma unroll
            for (int nb = 0; nb < 8; nb++) {
                const float* kp = &sK[nb * 8 + lg][16 * ks + 2 * lt];
                float2 b0 = *(const float2*)(kp);
                float2 b1 = *(const float2*)(kp + 8);
                uint32_t bh[2], bl[2];
                split_pair(b0.x, b0.y, bh[0], bl[0]);
                split_pair(b1.x, b1.y, bh[1], bl[1]);
                mma_bf16(s[nb], qh[ks], bh);
                mma_bf16(s[nb], qh[ks], bl);
                mma_bf16(s[nb], ql[ks], bh);
            }
        }

        // ---- causal mask (diagonal tile) ----
        if (kt == qt) {
            #pragma unroll
            for (int nb = 0; nb < 8; nb++) {
                int col = k0 + nb * 8 + 2 * lt;
                int rlo = qrow + lg, rhi = qrow + lg + 8;
                if (col     > rlo) s[nb][0] = -1e30f;
                if (col + 1 > rlo) s[nb][1] = -1e30f;
                if (col     > rhi) s[nb][2] = -1e30f;
                if (col + 1 > rhi) s[nb][3] = -1e30f;
            }
        }

        // ---- online softmax in registers ----
        float tm_lo = -1e30f, tm_hi = -1e30f;
        #pragma unroll
        for (int nb = 0; nb < 8; nb++) {
            tm_lo = fmaxf(tm_lo, fmaxf(s[nb][0], s[nb][1]));
            tm_hi = fmaxf(tm_hi, fmaxf(s[nb][2], s[nb][3]));
        }
        #pragma unroll
        for (int off = 1; off <= 2; off <<= 1) {
            tm_lo = fmaxf(tm_lo, __shfl_xor_sync(0xffffffffu, tm_lo, off));
            tm_hi = fmaxf(tm_hi, __shfl_xor_sync(0xffffffffu, tm_hi, off));
        }
        float mn_lo = fmaxf(m_lo, tm_lo);
        float mn_hi = fmaxf(m_hi, tm_hi);
        float sc_lo = exp2f(m_lo - mn_lo);
        float sc_hi = exp2f(m_hi - mn_hi);
        m_lo = mn_lo; m_hi = mn_hi;

        float ps_lo = 0.f, ps_hi = 0.f;
        #pragma unroll
        for (int nb = 0; nb < 8; nb++) {
            s[nb][0] = exp2f(s[nb][0] - mn_lo);
            s[nb][1] = exp2f(s[nb][1] - mn_lo);
            s[nb][2] = exp2f(s[nb][2] - mn_hi);
            s[nb][3] = exp2f(s[nb][3] - mn_hi);
            ps_lo += s[nb][0] + s[nb][1];
            ps_hi += s[nb][2] + s[nb][3];
        }
        l_lo = l_lo * sc_lo + ps_lo;
        l_hi = l_hi * sc_hi + ps_hi;
        #pragma unroll
        for (int nbd = 0; nbd < 8; nbd++) {
            o[nbd][0] *= sc_lo; o[nbd][1] *= sc_lo;
            o[nbd][2] *= sc_hi; o[nbd][3] *= sc_hi;
        }

        // ---- O += P @ V (P acc-layout == A-frag layout; split-bf16) ----
        #pragma unroll
        for (int kb = 0; kb < 4; kb++) {
            uint32_t ph[4], pl[4];
            split_pair(s[2*kb][0],     s[2*kb][1],     ph[0], pl[0]);
            split_pair(s[2*kb][2],     s[2*kb][3],     ph[1], pl[1]);
            split_pair(s[2*kb + 1][0], s[2*kb + 1][1], ph[2], pl[2]);
            split_pair(s[2*kb + 1][2], s[2*kb + 1][3], ph[3], pl[3]);
            const int krow = kb * 16 + 2 * lt;
            #pragma unroll
            for (int nbd = 0; nbd < 8; nbd++) {
                const int dcol = nbd * 8 + lg;
                float v0 = sV[krow][dcol],     v1 = sV[krow + 1][dcol];
                float v2 = sV[krow + 8][dcol], v3 = sV[krow + 9][dcol];
                uint32_t vh[2], vl[2];
                split_pair(v0, v1, vh[0], vl[0]);
                split_pair(v2, v3, vh[1], vl[1]);
                mma_bf16(o[nbd], ph, vh);
                mma_bf16(o[nbd], ph, vl);
                mma_bf16(o[nbd], pl, vh);
            }
        }
    }

    // ---- finalize: quad-reduce l, normalize, write ----
    #pragma unroll
    for (int off = 1; off <= 2; off <<= 1) {
        l_lo += __shfl_xor_sync(0xffffffffu, l_lo, off);
        l_hi += __shfl_xor_sync(0xffffffffu, l_hi, off);
    }
    float inv_lo = 1.0f / l_lo, inv_hi = 1.0f / l_hi;
    float* op = g_attn + (size_t)(b * SEQ + qrow) * EMB + h * HD;
    #pragma unroll
    for (int nbd = 0; nbd < 8; nbd++) {
        int dcol = nbd * 8 + 2 * lt;
        *(float2*)(op + (size_t)lg * EMB + dcol) =
            make_float2(o[nbd][0] * inv_lo, o[nbd][1] * inv_lo);
        *(float2*)(op + (size_t)(lg + 8) * EMB + dcol) =
            make_float2(o[nbd][2] * inv_hi, o[nbd][3] * inv_hi);
    }
}

// ---------------------------------------------------------------------------
extern "C" void kernel_launch(void* const* d_in, const int* in_sizes, int n_in,
                              void* d_out, int out_size)
{
    const float* x  = (const float*)d_in[0];
    const float* Wq = (const float*)d_in[1];
    const float* Wk = (const float*)d_in[2];
    const float* Wv = (const float*)d_in[3];
    const float* Wo = (const float*)d_in[4];
    float* out = (float*)d_out;

    cudaFuncSetAttribute(k_proj_qkv, cudaFuncAttributeMaxDynamicSharedMemorySize, SMEM_GEMM);
    cudaFuncSetAttribute(k_out_proj, cudaFuncAttributeMaxDynamicSharedMemorySize, SMEM_GEMM);

    k_proj_qkv<<<dim3(24, MTOT / BM), 256, SMEM_GEMM>>>(x, Wq, Wk, Wv);
    attn_tc<<<dim3(SEQ / 64, NH, BSZ), 128>>>();
    k_out_proj<<<dim3(EMB / BN, MTOT / BM), 256, SMEM_GEMM>>>(Wo, out);
}

// round 11
// speedup vs baseline: 3.3008x; 1.1674x over previous
#include <cuda_runtime.h>
#include <math.h>
#include <stdint.h>

// Problem constants
#define BSZ   2
#define SEQ   2048
#define EMB   2048
#define NH    32
#define HD    64
#define KVHN  8
#define KVD   512
#define GRP   4
#define MTOT  (BSZ*SEQ)   // 4096

// Scratch — device globals, referenced ONLY inside device code.
__device__ __align__(16) float g_q[MTOT * EMB];
__device__ __align__(16) float g_k[MTOT * KVD];
__device__ __align__(16) float g_v[MTOT * KVD];
__device__ __align__(16) float g_attn[MTOT * EMB];

// ---------------------------------------------------------------------------
// PTX helpers
// ---------------------------------------------------------------------------
__device__ __forceinline__ uint32_t pack_bf16x2(float v0, float v1) {
    uint32_t r;
    asm("cvt.rn.bf16x2.f32 %0, %1, %2;" : "=r"(r) : "f"(v1), "f"(v0));
    return r;
}
__device__ __forceinline__ void split_pair(float v0, float v1, uint32_t& hi, uint32_t& lo) {
    hi = pack_bf16x2(v0, v1);
    float h0 = __uint_as_float(hi << 16);
    float h1 = __uint_as_float(hi & 0xffff0000u);
    lo = pack_bf16x2(v0 - h0, v1 - h1);
}
__device__ __forceinline__ void mma_bf16(float* c, const uint32_t* a, const uint32_t* b) {
    asm volatile(
        "mma.sync.aligned.m16n8k16.row.col.f32.bf16.bf16.f32 "
        "{%0,%1,%2,%3},{%4,%5,%6,%7},{%8,%9},{%0,%1,%2,%3};"
        : "+f"(c[0]), "+f"(c[1]), "+f"(c[2]), "+f"(c[3])
        : "r"(a[0]), "r"(a[1]), "r"(a[2]), "r"(a[3]), "r"(b[0]), "r"(b[1]));
}

// ---------------------------------------------------------------------------
// Split-bf16 tensor-core GEMM v2: conversion hoisted to smem fill.
// C[M,N] = A[M,K] @ B[K,N]; block tile 128x128, BK=32, 256 threads (8 warps 2x4).
// bf16 hi/lo tiles in smem, register-prefetch double buffering, 1 sync/chunk.
// ---------------------------------------------------------------------------
#define BM 128
#define BN 128
#define BK 32
// smem (uint16 elems): Ah[2][128*40], Al, Bh[2][32*136], Bl
#define A_ST   5120     // stage stride (128*40)
#define B_ST   4352     // stage stride (32*136)
#define OFF_AL (2*A_ST)
#define OFF_BH (4*A_ST)
#define OFF_BL (4*A_ST + 2*B_ST)
#define SMEM_GEMM ((4*A_ST + 4*B_ST) * 2)   // 75776 B

__device__ __forceinline__
void gemm_body(const float* __restrict__ A, const float* __restrict__ Bg,
               float* __restrict__ C, int N, int K, int bx)
{
    extern __shared__ char smraw[];
    uint16_t* Ah = (uint16_t*)smraw;
    uint16_t* Al = Ah + OFF_AL;
    uint16_t* Bh = Ah + OFF_BH;
    uint16_t* Bl = Ah + OFF_BL;

    const int tid  = threadIdx.x;
    const int lane = tid & 31;
    const int wid  = tid >> 5;
    const int wm   = wid & 1;
    const int wn   = wid >> 1;
    const int m0   = blockIdx.y * BM;
    const int n0   = bx * BN;
    const int lg   = lane >> 2;
    const int lt   = lane & 3;

    // per-thread fill coordinates
    int aR[4], aK[4], bR[4], bC[4];
    #pragma unroll
    for (int i = 0; i < 4; i++) {
        int idx4 = tid + i * 256;       // 0..1023
        aR[i] = idx4 >> 3;              // 0..127
        aK[i] = (idx4 & 7) * 4;         // 0..28
        bR[i] = idx4 >> 5;              // 0..31
        bC[i] = (idx4 & 31) * 4;        // 0..124
    }

    float4 pa[4], pb[4];
    #pragma unroll
    for (int i = 0; i < 4; i++) {
        pa[i] = *(const float4*)(A  + (size_t)(m0 + aR[i]) * K + aK[i]);
        pb[i] = *(const float4*)(Bg + (size_t)bR[i] * N + n0 + bC[i]);
    }

    float acc[4][4][4] = {};
    const int nk = K / BK;

    for (int c = 0; c < nk; c++) {
        const int cur = c & 1;
        // ---- convert + store current chunk ----
        #pragma unroll
        for (int i = 0; i < 4; i++) {
            uint32_t h01, l01, h23, l23;
            split_pair(pa[i].x, pa[i].y, h01, l01);
            split_pair(pa[i].z, pa[i].w, h23, l23);
            int offA = cur * A_ST + aR[i] * 40 + aK[i];
            *(uint2*)(Ah + offA) = make_uint2(h01, h23);
            *(uint2*)(Al + offA) = make_uint2(l01, l23);

            split_pair(pb[i].x, pb[i].y, h01, l01);
            split_pair(pb[i].z, pb[i].w, h23, l23);
            int offB = cur * B_ST + bR[i] * 136 + bC[i];
            *(uint2*)(Bh + offB) = make_uint2(h01, h23);
            *(uint2*)(Bl + offB) = make_uint2(l01, l23);
        }
        // ---- prefetch next chunk (overlaps mma) ----
        if (c + 1 < nk) {
            #pragma unroll
            for (int i = 0; i < 4; i++) {
                pa[i] = *(const float4*)(A  + (size_t)(m0 + aR[i]) * K + (c + 1) * BK + aK[i]);
                pb[i] = *(const float4*)(Bg + (size_t)((c + 1) * BK + bR[i]) * N + n0 + bC[i]);
            }
        }
        __syncthreads();

        // ---- mma from bf16 smem ----
        const uint16_t* aH = Ah + cur * A_ST + (wm * 64) * 40;
        const uint16_t* aL = Al + cur * A_ST + (wm * 64) * 40;
        const uint16_t* bH = Bh + cur * B_ST + wn * 32;
        const uint16_t* bL = Bl + cur * B_ST + wn * 32;

        #pragma unroll
        for (int ks = 0; ks < 2; ks++) {
            const int k = ks * 16;
            uint32_t ah[4][4], al[4][4];
            #pragma unroll
            for (int mi = 0; mi < 4; mi++) {
                const uint16_t* ap = aH + (mi * 16 + lg) * 40 + k + 2 * lt;
                const uint16_t* aq = aL + (mi * 16 + lg) * 40 + k + 2 * lt;
                ah[mi][0] = *(const uint32_t*)(ap);
                ah[mi][1] = *(const uint32_t*)(ap + 320);
                ah[mi][2] = *(const uint32_t*)(ap + 8);
                ah[mi][3] = *(const uint32_t*)(ap + 328);
                al[mi][0] = *(const uint32_t*)(aq);
                al[mi][1] = *(const uint32_t*)(aq + 320);
                al[mi][2] = *(const uint32_t*)(aq + 8);
                al[mi][3] = *(const uint32_t*)(aq + 328);
            }
            #pragma unroll
            for (int ni = 0; ni < 4; ni++) {
                const uint16_t* bp = bH + (k + 2 * lt) * 136 + ni * 8 + lg;
                const uint16_t* bq = bL + (k + 2 * lt) * 136 + ni * 8 + lg;
                uint32_t bh[2], bl[2];
                bh[0] = (uint32_t)bp[0]    | ((uint32_t)bp[136]  << 16);
                bh[1] = (uint32_t)bp[1088] | ((uint32_t)bp[1224] << 16);
                bl[0] = (uint32_t)bq[0]    | ((uint32_t)bq[136]  << 16);
                bl[1] = (uint32_t)bq[1088] | ((uint32_t)bq[1224] << 16);
                #pragma unroll
                for (int mi = 0; mi < 4; mi++) {
                    mma_bf16(acc[mi][ni], ah[mi], bh);
                    mma_bf16(acc[mi][ni], ah[mi], bl);
                    mma_bf16(acc[mi][ni], al[mi], bh);
                }
            }
        }
    }

    // ---- store C ----
    #pragma unroll
    for (int mi = 0; mi < 4; mi++) {
        #pragma unroll
        for (int ni = 0; ni < 4; ni++) {
            int row = m0 + wm * 64 + mi * 16 + lg;
            int col = n0 + wn * 32 + ni * 8 + 2 * lt;
            float2 v0 = make_float2(acc[mi][ni][0], acc[mi][ni][1]);
            float2 v1 = make_float2(acc[mi][ni][2], acc[mi][ni][3]);
            *(float2*)(C + (size_t)row * N + col)       = v0;
            *(float2*)(C + (size_t)(row + 8) * N + col) = v1;
        }
    }
}

// Fused Q/K/V projection: grid.x 0..15 -> Q, 16..19 -> K, 20..23 -> V
__global__ __launch_bounds__(256)
void k_proj_qkv(const float* __restrict__ x, const float* __restrict__ Wq,
                const float* __restrict__ Wk, const float* __restrict__ Wv) {
    int bx = blockIdx.x;
    if (bx < 16)      gemm_body(x, Wq, g_q, EMB, EMB, bx);
    else if (bx < 20) gemm_body(x, Wk, g_k, KVD, EMB, bx - 16);
    else              gemm_body(x, Wv, g_v, KVD, EMB, bx - 20);
}
__global__ __launch_bounds__(256)
void k_out_proj(const float* __restrict__ Wo, float* __restrict__ out) {
    gemm_body(g_attn, Wo, out, EMB, EMB, blockIdx.x);
}

// ---------------------------------------------------------------------------
// Tensor-core causal GQA flash attention (R10-proven, unchanged).
// ---------------------------------------------------------------------------
#define APK 72
#define APV 68

__global__ __launch_bounds__(128)
void attn_tc()
{
    __shared__ float sK[64][APK];
    __shared__ float sV[64][APV];

    const int qt = blockIdx.x, h = blockIdx.y, b = blockIdx.z;
    const int kvh = h >> 2;
    const int tid = threadIdx.x;
    const int w = tid >> 5, lane = tid & 31;
    const int lg = lane >> 2, lt = lane & 3;
    const int q0 = qt * 64;
    const int qrow = q0 + w * 16;
    const float qscale = 0.125f * 1.44269504f;

    uint32_t qh[4][4], ql[4][4];
    {
        const float* qp = g_q + (size_t)(b * SEQ + qrow) * EMB + h * HD;
        #pragma unroll
        for (int ks = 0; ks < 4; ks++) {
            int d0 = ks * 16 + 2 * lt;
            float2 v00 = *(const float2*)(qp + (size_t)lg * EMB + d0);
            float2 v10 = *(const float2*)(qp + (size_t)(lg + 8) * EMB + d0);
            float2 v01 = *(const float2*)(qp + (size_t)lg * EMB + d0 + 8);
            float2 v11 = *(const float2*)(qp + (size_t)(lg + 8) * EMB + d0 + 8);
            split_pair(v00.x * qscale, v00.y * qscale, qh[ks][0], ql[ks][0]);
            split_pair(v10.x * qscale, v10.y * qscale, qh[ks][1], ql[ks][1]);
            split_pair(v01.x * qscale, v01.y * qscale, qh[ks][2], ql[ks][2]);
            split_pair(v11.x * qscale, v11.y * qscale, qh[ks][3], ql[ks][3]);
        }
    }

    float m_lo = -1e30f, m_hi = -1e30f;
    float l_lo = 0.f, l_hi = 0.f;
    float o[8][4] = {};

    for (int kt = 0; kt <= qt; kt++) {
        const int k0 = kt * 64;
        __syncthreads();
        #pragma unroll
        for (int i = 0; i < 8; i++) {
            int idx = tid + i * 128;
            int r = idx >> 4, c4 = (idx & 15) * 4;
            size_t base = (size_t)(b * SEQ + k0 + r) * KVD + kvh * HD + c4;
            *(float4*)&sK[r][c4] = *(const float4*)(g_k + base);
            *(float4*)&sV[r][c4] = *(const float4*)(g_v + base);
        }
        __syncthreads();

        float s[8][4] = {};
        #pragma unroll
        for (int ks = 0; ks < 4; ks++) {
            #pragma unroll
            for (int nb = 0; nb < 8; nb++) {
                const float* kp = &sK[nb * 8 + lg][16 * ks + 2 * lt];
                float2 b0 = *(const float2*)(kp);
                float2 b1 = *(const float2*)(kp + 8);
                uint32_t bh[2], bl[2];
                split_pair(b0.x, b0.y, bh[0], bl[0]);
                split_pair(b1.x, b1.y, bh[1], bl[1]);
                mma_bf16(s[nb], qh[ks], bh);
                mma_bf16(s[nb], qh[ks], bl);
                mma_bf16(s[nb], ql[ks], bh);
            }
        }

        if (kt == qt) {
            #pragma unroll
            for (int nb = 0; nb < 8; nb++) {
                int col = k0 + nb * 8 + 2 * lt;
                int rlo = qrow + lg, rhi = qrow + lg + 8;
                if (col     > rlo) s[nb][0] = -1e30f;
                if (col + 1 > rlo) s[nb][1] = -1e30f;
                if (col     > rhi) s[nb][2] = -1e30f;
                if (col + 1 > rhi) s[nb][3] = -1e30f;
            }
        }

        float tm_lo = -1e30f, tm_hi = -1e30f;
        #pragma unroll
        for (int nb = 0; nb < 8; nb++) {
            tm_lo = fmaxf(tm_lo, fmaxf(s[nb][0], s[nb][1]));
            tm_hi = fmaxf(tm_hi, fmaxf(s[nb][2], s[nb][3]));
        }
        #pragma unroll
        for (int off = 1; off <= 2; off <<= 1) {
            tm_lo = fmaxf(tm_lo, __shfl_xor_sync(0xffffffffu, tm_lo, off));
            tm_hi = fmaxf(tm_hi, __shfl_xor_sync(0xffffffffu, tm_hi, off));
        }
        float mn_lo = fmaxf(m_lo, tm_lo);
        float mn_hi = fmaxf(m_hi, tm_hi);
        float sc_lo = exp2f(m_lo - mn_lo);
        float sc_hi = exp2f(m_hi - mn_hi);
        m_lo = mn_lo; m_hi = mn_hi;

        float ps_lo = 0.f, ps_hi = 0.f;
        #pragma unroll
        for (int nb = 0; nb < 8; nb++) {
            s[nb][0] = exp2f(s[nb][0] - mn_lo);
            s[nb][1] = exp2f(s[nb][1] - mn_lo);
            s[nb][2] = exp2f(s[nb][2] - mn_hi);
            s[nb][3] = exp2f(s[nb][3] - mn_hi);
            ps_lo += s[nb][0] + s[nb][1];
            ps_hi += s[nb][2] + s[nb][3];
        }
        l_lo = l_lo * sc_lo + ps_lo;
        l_hi = l_hi * sc_hi + ps_hi;
        #pragma unroll
        for (int nbd = 0; nbd < 8; nbd++) {
            o[nbd][0] *= sc_lo; o[nbd][1] *= sc_lo;
            o[nbd][2] *= sc_hi; o[nbd][3] *= sc_hi;
        }

        #pragma unroll
        for (int kb = 0; kb < 4; kb++) {
            uint32_t ph[4], pl[4];
            split_pair(s[2*kb][0],     s[2*kb][1],     ph[0], pl[0]);
            split_pair(s[2*kb][2],     s[2*kb][3],     ph[1], pl[1]);
            split_pair(s[2*kb + 1][0], s[2*kb + 1][1], ph[2], pl[2]);
            split_pair(s[2*kb + 1][2], s[2*kb + 1][3], ph[3], pl[3]);
            const int krow = kb * 16 + 2 * lt;
            #pragma unroll
            for (int nbd = 0; nbd < 8; nbd++) {
                const int dcol = nbd * 8 + lg;
                float v0 = sV[krow][dcol],     v1 = sV[krow + 1][dcol];
                float v2 = sV[krow + 8][dcol], v3 = sV[krow + 9][dcol];
                uint32_t vh[2], vl[2];
                split_pair(v0, v1, vh[0], vl[0]);
                split_pair(v2, v3, vh[1], vl[1]);
                mma_bf16(o[nbd], ph, vh);
                mma_bf16(o[nbd], ph, vl);
                mma_bf16(o[nbd], pl, vh);
            }
        }
    }

    #pragma unroll
    for (int off = 1; off <= 2; off <<= 1) {
        l_lo += __shfl_xor_sync(0xffffffffu, l_lo, off);
        l_hi += __shfl_xor_sync(0xffffffffu, l_hi, off);
    }
    float inv_lo = 1.0f / l_lo, inv_hi = 1.0f / l_hi;
    float* op = g_attn + (size_t)(b * SEQ + qrow) * EMB + h * HD;
    #pragma unroll
    for (int nbd = 0; nbd < 8; nbd++) {
        int dcol = nbd * 8 + 2 * lt;
        *(float2*)(op + (size_t)lg * EMB + dcol) =
            make_float2(o[nbd][0] * inv_lo, o[nbd][1] * inv_lo);
        *(float2*)(op + (size_t)(lg + 8) * EMB + dcol) =
            make_float2(o[nbd][2] * inv_hi, o[nbd][3] * inv_hi);
    }
}

// ---------------------------------------------------------------------------
extern "C" void kernel_launch(void* const* d_in, const int* in_sizes, int n_in,
                              void* d_out, int out_size)
{
    const float* x  = (const float*)d_in[0];
    const float* Wq = (const float*)d_in[1];
    const float* Wk = (const float*)d_in[2];
    const float* Wv = (const float*)d_in[3];
    const float* Wo = (const float*)d_in[4];
    float* out = (float*)d_out;

    cudaFuncSetAttribute(k_proj_qkv, cudaFuncAttributeMaxDynamicSharedMemorySize, SMEM_GEMM);
    cudaFuncSetAttribute(k_out_proj, cudaFuncAttributeMaxDynamicSharedMemorySize, SMEM_GEMM);

    k_proj_qkv<<<dim3(24, MTOT / BM), 256, SMEM_GEMM>>>(x, Wq, Wk, Wv);
    attn_tc<<<dim3(SEQ / 64, NH, BSZ), 128>>>();
    k_out_proj<<<dim3(EMB / BN, MTOT / BM), 256, SMEM_GEMM>>>(Wo, out);
}

// round 12
// speedup vs baseline: 3.6475x; 1.1050x over previous
#include <cuda_runtime.h>
#include <math.h>
#include <stdint.h>

// Problem constants
#define BSZ   2
#define SEQ   2048
#define EMB   2048
#define NH    32
#define HD    64
#define KVHN  8
#define KVD   512
#define GRP   4
#define MTOT  (BSZ*SEQ)   // 4096

// Scratch — device globals, referenced ONLY inside device code.
__device__ __align__(16) float g_q[MTOT * EMB];
__device__ __align__(16) float g_k[MTOT * KVD];
__device__ __align__(16) float g_v[MTOT * KVD];
__device__ __align__(16) float g_attn[MTOT * EMB];

// ---------------------------------------------------------------------------
// PTX helpers
// ---------------------------------------------------------------------------
__device__ __forceinline__ uint32_t smem_u32(const void* p) {
    return (uint32_t)__cvta_generic_to_shared(p);
}
__device__ __forceinline__ uint32_t pack_bf16x2(float v0, float v1) {
    uint32_t r;
    asm("cvt.rn.bf16x2.f32 %0, %1, %2;" : "=r"(r) : "f"(v1), "f"(v0));
    return r;
}
__device__ __forceinline__ void split_pair(float v0, float v1, uint32_t& hi, uint32_t& lo) {
    hi = pack_bf16x2(v0, v1);
    float h0 = __uint_as_float(hi << 16);
    float h1 = __uint_as_float(hi & 0xffff0000u);
    lo = pack_bf16x2(v0 - h0, v1 - h1);
}
__device__ __forceinline__ void mma_bf16(float* c, const uint32_t* a, const uint32_t* b) {
    asm volatile(
        "mma.sync.aligned.m16n8k16.row.col.f32.bf16.bf16.f32 "
        "{%0,%1,%2,%3},{%4,%5,%6,%7},{%8,%9},{%0,%1,%2,%3};"
        : "+f"(c[0]), "+f"(c[1]), "+f"(c[2]), "+f"(c[3])
        : "r"(a[0]), "r"(a[1]), "r"(a[2]), "r"(a[3]), "r"(b[0]), "r"(b[1]));
}
__device__ __forceinline__ void ldsm4(uint32_t* r, uint32_t addr) {
    asm volatile("ldmatrix.sync.aligned.m8n8.x4.shared.b16 {%0,%1,%2,%3}, [%4];"
        : "=r"(r[0]), "=r"(r[1]), "=r"(r[2]), "=r"(r[3]) : "r"(addr));
}
__device__ __forceinline__ void ldsm2t(uint32_t* r, uint32_t addr) {
    asm volatile("ldmatrix.sync.aligned.m8n8.x2.trans.shared.b16 {%0,%1}, [%2];"
        : "=r"(r[0]), "=r"(r[1]) : "r"(addr));
}

// ---------------------------------------------------------------------------
// Split-bf16 tensor-core GEMM v3: bf16 hi/lo smem tiles + LDSM fragment loads.
// C[M,N] = A[M,K] @ B[K,N]; block tile 128x128, BK=32, 256 threads (8 warps 2x4).
// ---------------------------------------------------------------------------
#define BM 128
#define BN 128
#define BK 32
#define A_ST   5120     // stage stride, uint16 elems (128*40)
#define B_ST   4352     // stage stride, uint16 elems (32*136)
#define OFF_AL (2*A_ST)
#define OFF_BH (4*A_ST)
#define OFF_BL (4*A_ST + 2*B_ST)
#define SMEM_GEMM ((4*A_ST + 4*B_ST) * 2)   // 75776 B

__device__ __forceinline__
void gemm_body(const float* __restrict__ A, const float* __restrict__ Bg,
               float* __restrict__ C, int N, int K, int bx)
{
    extern __shared__ char smraw[];
    uint16_t* Ah = (uint16_t*)smraw;
    uint16_t* Al = Ah + OFF_AL;
    uint16_t* Bh = Ah + OFF_BH;
    uint16_t* Bl = Ah + OFF_BL;

    const int tid  = threadIdx.x;
    const int lane = tid & 31;
    const int wid  = tid >> 5;
    const int wm   = wid & 1;
    const int wn   = wid >> 1;
    const int m0   = blockIdx.y * BM;
    const int n0   = bx * BN;
    const int lg   = lane >> 2;
    const int lt   = lane & 3;

    // LDSM lane-address components (byte offsets)
    const int rowA = ((lane >> 3) & 1) * 8 + (lane & 7);
    const int colA = (lane >> 4) * 8;
    const uint32_t aLane = (uint32_t)(rowA * 40 + colA) * 2;
    const uint32_t bLane = (uint32_t)((lane & 15) * 136) * 2;

    const uint32_t ahB0 = smem_u32(Ah);
    const uint32_t alB0 = smem_u32(Al);
    const uint32_t bhB0 = smem_u32(Bh);
    const uint32_t blB0 = smem_u32(Bl);

    // per-thread fill coordinates
    int aR[4], aK[4], bR[4], bC[4];
    #pragma unroll
    for (int i = 0; i < 4; i++) {
        int idx4 = tid + i * 256;       // 0..1023
        aR[i] = idx4 >> 3;              // 0..127
        aK[i] = (idx4 & 7) * 4;         // 0..28
        bR[i] = idx4 >> 5;              // 0..31
        bC[i] = (idx4 & 31) * 4;        // 0..124
    }

    float4 pa[4], pb[4];
    #pragma unroll
    for (int i = 0; i < 4; i++) {
        pa[i] = *(const float4*)(A  + (size_t)(m0 + aR[i]) * K + aK[i]);
        pb[i] = *(const float4*)(Bg + (size_t)bR[i] * N + n0 + bC[i]);
    }

    float acc[4][4][4] = {};
    const int nk = K / BK;

    for (int c = 0; c < nk; c++) {
        const int cur = c & 1;
        // ---- convert + store current chunk ----
        #pragma unroll
        for (int i = 0; i < 4; i++) {
            uint32_t h01, l01, h23, l23;
            split_pair(pa[i].x, pa[i].y, h01, l01);
            split_pair(pa[i].z, pa[i].w, h23, l23);
            int offA = cur * A_ST + aR[i] * 40 + aK[i];
            *(uint2*)(Ah + offA) = make_uint2(h01, h23);
            *(uint2*)(Al + offA) = make_uint2(l01, l23);

            split_pair(pb[i].x, pb[i].y, h01, l01);
            split_pair(pb[i].z, pb[i].w, h23, l23);
            int offB = cur * B_ST + bR[i] * 136 + bC[i];
            *(uint2*)(Bh + offB) = make_uint2(h01, h23);
            *(uint2*)(Bl + offB) = make_uint2(l01, l23);
        }
        // ---- prefetch next chunk (overlaps mma) ----
        if (c + 1 < nk) {
            #pragma unroll
            for (int i = 0; i < 4; i++) {
                pa[i] = *(const float4*)(A  + (size_t)(m0 + aR[i]) * K + (c + 1) * BK + aK[i]);
                pb[i] = *(const float4*)(Bg + (size_t)((c + 1) * BK + bR[i]) * N + n0 + bC[i]);
            }
        }
        __syncthreads();

        // ---- mma from bf16 smem via LDSM ----
        const uint32_t ahB = ahB0 + cur * (A_ST * 2) + (wm * 64 * 40) * 2 + aLane;
        const uint32_t alB = alB0 + cur * (A_ST * 2) + (wm * 64 * 40) * 2 + aLane;
        const uint32_t bhB = bhB0 + cur * (B_ST * 2) + (wn * 32) * 2 + bLane;
        const uint32_t blB = blB0 + cur * (B_ST * 2) + (wn * 32) * 2 + bLane;

        #pragma unroll
        for (int ks = 0; ks < 2; ks++) {
            const int k = ks * 16;
            uint32_t ah[4][4], al[4][4];
            #pragma unroll
            for (int mi = 0; mi < 4; mi++) {
                uint32_t off = (uint32_t)(mi * 16 * 40 + k) * 2;
                ldsm4(ah[mi], ahB + off);
                ldsm4(al[mi], alB + off);
            }
            #pragma unroll
            for (int ni = 0; ni < 4; ni++) {
                uint32_t off = (uint32_t)(k * 136 + ni * 8) * 2;
                uint32_t bh[2], bl[2];
                ldsm2t(bh, bhB + off);
                ldsm2t(bl, blB + off);
                #pragma unroll
                for (int mi = 0; mi < 4; mi++) {
                    mma_bf16(acc[mi][ni], ah[mi], bh);
                    mma_bf16(acc[mi][ni], ah[mi], bl);
                    mma_bf16(acc[mi][ni], al[mi], bh);
                }
            }
        }
    }

    // ---- store C ----
    #pragma unroll
    for (int mi = 0; mi < 4; mi++) {
        #pragma unroll
        for (int ni = 0; ni < 4; ni++) {
            int row = m0 + wm * 64 + mi * 16 + lg;
            int col = n0 + wn * 32 + ni * 8 + 2 * lt;
            float2 v0 = make_float2(acc[mi][ni][0], acc[mi][ni][1]);
            float2 v1 = make_float2(acc[mi][ni][2], acc[mi][ni][3]);
            *(float2*)(C + (size_t)row * N + col)       = v0;
            *(float2*)(C + (size_t)(row + 8) * N + col) = v1;
        }
    }
}

// Fused Q/K/V projection: grid.x 0..15 -> Q, 16..19 -> K, 20..23 -> V
__global__ __launch_bounds__(256)
void k_proj_qkv(const float* __restrict__ x, const float* __restrict__ Wq,
                const float* __restrict__ Wk, const float* __restrict__ Wv) {
    int bx = blockIdx.x;
    if (bx < 16)      gemm_body(x, Wq, g_q, EMB, EMB, bx);
    else if (bx < 20) gemm_body(x, Wk, g_k, KVD, EMB, bx - 16);
    else              gemm_body(x, Wv, g_v, KVD, EMB, bx - 20);
}
__global__ __launch_bounds__(256)
void k_out_proj(const float* __restrict__ Wo, float* __restrict__ out) {
    gemm_body(g_attn, Wo, out, EMB, EMB, blockIdx.x);
}

// ---------------------------------------------------------------------------
// Tensor-core causal GQA flash attention (R10-proven, unchanged).
// ---------------------------------------------------------------------------
#define APK 72
#define APV 68

__global__ __launch_bounds__(128)
void attn_tc()
{
    __shared__ float sK[64][APK];
    __shared__ float sV[64][APV];

    const int qt = blockIdx.x, h = blockIdx.y, b = blockIdx.z;
    const int kvh = h >> 2;
    const int tid = threadIdx.x;
    const int w = tid >> 5, lane = tid & 31;
    const int lg = lane >> 2, lt = lane & 3;
    const int q0 = qt * 64;
    const int qrow = q0 + w * 16;
    const float qscale = 0.125f * 1.44269504f;

    uint32_t qh[4][4], ql[4][4];
    {
        const float* qp = g_q + (size_t)(b * SEQ + qrow) * EMB + h * HD;
        #pragma unroll
        for (int ks = 0; ks < 4; ks++) {
            int d0 = ks * 16 + 2 * lt;
            float2 v00 = *(const float2*)(qp + (size_t)lg * EMB + d0);
            float2 v10 = *(const float2*)(qp + (size_t)(lg + 8) * EMB + d0);
            float2 v01 = *(const float2*)(qp + (size_t)lg * EMB + d0 + 8);
            float2 v11 = *(const float2*)(qp + (size_t)(lg + 8) * EMB + d0 + 8);
            split_pair(v00.x * qscale, v00.y * qscale, qh[ks][0], ql[ks][0]);
            split_pair(v10.x * qscale, v10.y * qscale, qh[ks][1], ql[ks][1]);
            split_pair(v01.x * qscale, v01.y * qscale, qh[ks][2], ql[ks][2]);
            split_pair(v11.x * qscale, v11.y * qscale, qh[ks][3], ql[ks][3]);
        }
    }

    float m_lo = -1e30f, m_hi = -1e30f;
    float l_lo = 0.f, l_hi = 0.f;
    float o[8][4] = {};

    for (int kt = 0; kt <= qt; kt++) {
        const int k0 = kt * 64;
        __syncthreads();
        #pragma unroll
        for (int i = 0; i < 8; i++) {
            int idx = tid + i * 128;
            int r = idx >> 4, c4 = (idx & 15) * 4;
            size_t base = (size_t)(b * SEQ + k0 + r) * KVD + kvh * HD + c4;
            *(float4*)&sK[r][c4] = *(const float4*)(g_k + base);
            *(float4*)&sV[r][c4] = *(const float4*)(g_v + base);
        }
        __syncthreads();

        float s[8][4] = {};
        #pragma unroll
        for (int ks = 0; ks < 4; ks++) {
            #pragma unroll
            for (int nb = 0; nb < 8; nb++) {
                const float* kp = &sK[nb * 8 + lg][16 * ks + 2 * lt];
                float2 b0 = *(const float2*)(kp);
                float2 b1 = *(const float2*)(kp + 8);
                uint32_t bh[2], bl[2];
                split_pair(b0.x, b0.y, bh[0], bl[0]);
                split_pair(b1.x, b1.y, bh[1], bl[1]);
                mma_bf16(s[nb], qh[ks], bh);
                mma_bf16(s[nb], qh[ks], bl);
                mma_bf16(s[nb], ql[ks], bh);
            }
        }

        if (kt == qt) {
            #pragma unroll
            for (int nb = 0; nb < 8; nb++) {
                int col = k0 + nb * 8 + 2 * lt;
                int rlo = qrow + lg, rhi = qrow + lg + 8;
                if (col     > rlo) s[nb][0] = -1e30f;
                if (col + 1 > rlo) s[nb][1] = -1e30f;
                if (col     > rhi) s[nb][2] = -1e30f;
                if (col + 1 > rhi) s[nb][3] = -1e30f;
            }
        }

        float tm_lo = -1e30f, tm_hi = -1e30f;
        #pragma unroll
        for (int nb = 0; nb < 8; nb++) {
            tm_lo = fmaxf(tm_lo, fmaxf(s[nb][0], s[nb][1]));
            tm_hi = fmaxf(tm_hi, fmaxf(s[nb][2], s[nb][3]));
        }
        #pragma unroll
        for (int off = 1; off <= 2; off <<= 1) {
            tm_lo = fmaxf(tm_lo, __shfl_xor_sync(0xffffffffu, tm_lo, off));
            tm_hi = fmaxf(tm_hi, __shfl_xor_sync(0xffffffffu, tm_hi, off));
        }
        float mn_lo = fmaxf(m_lo, tm_lo);
        float mn_hi = fmaxf(m_hi, tm_hi);
        float sc_lo = exp2f(m_lo - mn_lo);
        float sc_hi = exp2f(m_hi - mn_hi);
        m_lo = mn_lo; m_hi = mn_hi;

        float ps_lo = 0.f, ps_hi = 0.f;
        #pragma unroll
        for (int nb = 0; nb < 8; nb++) {
            s[nb][0] = exp2f(s[nb][0] - mn_lo);
            s[nb][1] = exp2f(s[nb][1] - mn_lo);
            s[nb][2] = exp2f(s[nb][2] - mn_hi);
            s[nb][3] = exp2f(s[nb][3] - mn_hi);
            ps_lo += s[nb][0] + s[nb][1];
            ps_hi += s[nb][2] + s[nb][3];
        }
        l_lo = l_lo * sc_lo + ps_lo;
        l_hi = l_hi * sc_hi + ps_hi;
        #pragma unroll
        for (int nbd = 0; nbd < 8; nbd++) {
            o[nbd][0] *= sc_lo; o[nbd][1] *= sc_lo;
            o[nbd][2] *= sc_hi; o[nbd][3] *= sc_hi;
        }

        #pragma unroll
        for (int kb = 0; kb < 4; kb++) {
            uint32_t ph[4], pl[4];
            split_pair(s[2*kb][0],     s[2*kb][1],     ph[0], pl[0]);
            split_pair(s[2*kb][2],     s[2*kb][3],     ph[1], pl[1]);
            split_pair(s[2*kb + 1][0], s[2*kb + 1][1], ph[2], pl[2]);
            split_pair(s[2*kb + 1][2], s[2*kb + 1][3], ph[3], pl[3]);
            const int krow = kb * 16 + 2 * lt;
            #pragma unroll
            for (int nbd = 0; nbd < 8; nbd++) {
                const int dcol = nbd * 8 + lg;
                float v0 = sV[krow][dcol],     v1 = sV[krow + 1][dcol];
                float v2 = sV[krow + 8][dcol], v3 = sV[krow + 9][dcol];
                uint32_t vh[2], vl[2];
                split_pair(v0, v1, vh[0], vl[0]);
                split_pair(v2, v3, vh[1], vl[1]);
                mma_bf16(o[nbd], ph, vh);
                mma_bf16(o[nbd], ph, vl);
                mma_bf16(o[nbd], pl, vh);
            }
        }
    }

    #pragma unroll
    for (int off = 1; off <= 2; off <<= 1) {
        l_lo += __shfl_xor_sync(0xffffffffu, l_lo, off);
        l_hi += __shfl_xor_sync(0xffffffffu, l_hi, off);
    }
    float inv_lo = 1.0f / l_lo, inv_hi = 1.0f / l_hi;
    float* op = g_attn + (size_t)(b * SEQ + qrow) * EMB + h * HD;
    #pragma unroll
    for (int nbd = 0; nbd < 8; nbd++) {
        int dcol = nbd * 8 + 2 * lt;
        *(float2*)(op + (size_t)lg * EMB + dcol) =
            make_float2(o[nbd][0] * inv_lo, o[nbd][1] * inv_lo);
        *(float2*)(op + (size_t)(lg + 8) * EMB + dcol) =
            make_float2(o[nbd][2] * inv_hi, o[nbd][3] * inv_hi);
    }
}

// ---------------------------------------------------------------------------
extern "C" void kernel_launch(void* const* d_in, const int* in_sizes, int n_in,
                              void* d_out, int out_size)
{
    const float* x  = (const float*)d_in[0];
    const float* Wq = (const float*)d_in[1];
    const float* Wk = (const float*)d_in[2];
    const float* Wv = (const float*)d_in[3];
    const float* Wo = (const float*)d_in[4];
    float* out = (float*)d_out;

    cudaFuncSetAttribute(k_proj_qkv, cudaFuncAttributeMaxDynamicSharedMemorySize, SMEM_GEMM);
    cudaFuncSetAttribute(k_out_proj, cudaFuncAttributeMaxDynamicSharedMemorySize, SMEM_GEMM);

    k_proj_qkv<<<dim3(24, MTOT / BM), 256, SMEM_GEMM>>>(x, Wq, Wk, Wv);
    attn_tc<<<dim3(SEQ / 64, NH, BSZ), 128>>>();
    k_out_proj<<<dim3(EMB / BN, MTOT / BM), 256, SMEM_GEMM>>>(Wo, out);
}